// round 11
// baseline (speedup 1.0000x reference)
#include <cuda_runtime.h>

#define TPB 128
#define NH  40
#define NT  40
#define NG  160
#define NC  4
#define HBASE 3208   // floats per half-section: 80 rows * 40 + 8-float bank skew

typedef unsigned long long u64;

__device__ __forceinline__ u64 pack2(float lo, float hi) {
    u64 r; asm("mov.b64 %0, {%1, %2};" : "=l"(r) : "f"(lo), "f"(hi)); return r;
}
__device__ __forceinline__ float2 unpack2(u64 v) {
    float2 f; asm("mov.b64 {%0, %1}, %2;" : "=f"(f.x), "=f"(f.y) : "l"(v)); return f;
}
// Packed dual-fp32 FMA (Blackwell f32x2 pipe)
__device__ __forceinline__ u64 ffma2(u64 a, u64 b, u64 c) {
    u64 d; asm("fma.rn.f32x2 %0, %1, %2, %3;" : "=l"(d) : "l"(a), "l"(b), "l"(c)); return d;
}
__device__ __forceinline__ float rcpf(float a) {
    float r; asm("rcp.approx.f32 %0, %1;" : "=f"(r) : "f"(a)); return r;
}

// LSTM gate epilogue with batched reciprocal for the (i,f,g) trio:
// one MUFU.RCP replaces three (trio product bounded by ~3.4e9, overflow-safe).
// o-gate and tanh(c_new) keep private RCPs: 1+e^{2|c|} can reach ~5e34 and a
// batched product would flirt with fp32 overflow -> NaN tail risk.
// MUFU per call: 5 EX2 + 3 RCP (was 5 EX2 + 5 RCP).
__device__ __forceinline__ float lstm_epilogue(float gi, float gf, float gg,
                                               float go, float& c)
{
    const float t1 = __expf(-gi);
    const float t2 = __expf(-gf);
    const float t4 = __expf(-2.0f * gg);
    const float d1 = 1.0f + t1;
    const float d2 = 1.0f + t2;
    const float d4 = 1.0f + t4;
    const float e24 = d2 * d4;
    const float R  = rcpf(d1 * e24);
    const float si = R * e24;                       // sigmoid(gi)
    const float q  = R * d1;
    const float sf = q * d4;                        // sigmoid(gf)
    const float tg = fmaf(2.0f, q * d2, -1.0f);     // tanh(gg)
    const float cn = fmaf(sf, c, si * tg);
    c = cn;
    const float so = rcpf(1.0f + __expf(-go));      // sigmoid(go)
    const float th = fmaf(2.0f, rcpf(1.0f + __expf(-2.0f * cn)), -1.0f);
    return so * th;
}

__global__ __launch_bounds__(TPB, 3)
void lstm_head_kernel(const float* __restrict__ x,
                      const float* __restrict__ W_ih,
                      const float* __restrict__ W_hh,
                      const float* __restrict__ b_ih,
                      const float* __restrict__ b_hh,
                      const float* __restrict__ W_fc,
                      const float* __restrict__ b_fc,
                      float* __restrict__ out,
                      int write_logits, int write_argmax, long long arg_off)
{
    // W_hh split by unit-half: half h owns units [h*20, h*20+20).
    // Row (g, jj) of half h lives at Ws[h*HBASE + (g*20+jj)*40 .. +40).
    // HBASE skew (32B) keeps the two halves' 2-address broadcasts on disjoint banks.
    __shared__ __align__(16) float Ws[2 * HBASE];    // 25664 B
    __shared__ float2 winb_s[NG];                    // (W_ih[r], b_ih[r]+b_hh[r])
    __shared__ float  Wfc_s[NC * NH];
    __shared__ float  bfc_s[NC];
    __shared__ float2 hs[NH / 2][130];               // h staging [unit-pair][seq], padded
                                                     // (8B seq-stride: conflict-free)

    const int tid  = threadIdx.x;
    const int pair = tid >> 1;
    const int half = tid & 1;

    for (int i = tid; i < NG * NH; i += TPB) {
        int r = i / NH, k = i % NH;           // global row r = g*40 + j
        int g = r / NH, j = r % NH;
        int hh = j / 20, jj = j % 20;
        Ws[hh * HBASE + (g * 20 + jj) * NH + k] = W_hh[i];
    }
    for (int i = tid; i < NG; i += TPB)
        winb_s[i] = make_float2(W_ih[i], b_ih[i] + b_hh[i]);
    for (int i = tid; i < NC * NH; i += TPB) Wfc_s[i] = W_fc[i];
    if (tid < NC) bfc_s[tid] = b_fc[tid];
    __syncthreads();

    const long long base = (long long)blockIdx.x * TPB;  // 128 seqs per block
    const float* __restrict__ x0 = x + (base + 2 * pair) * NT;      // seq 2p
    const float* __restrict__ x1 = x0 + NT;                          // seq 2p+1

    const float* Wh = Ws + half * HBASE;
    const int jg = half * 20;     // first owned global unit

    u64 h0[NH / 2], h1[NH / 2];   // full packed h for seqs 2p, 2p+1
    float c0[20], c1[20];         // cell state, my 20 units only
#pragma unroll
    for (int k = 0; k < NH / 2; k++) { h0[k] = 0ULL; h1[k] = 0ULL; }
#pragma unroll
    for (int k = 0; k < 20; k++) { c0[k] = 0.0f; c1[k] = 0.0f; }

    float xa = x0[0];
    float xb = x1[0];

#pragma unroll 1
    for (int t = 0; t < NT; t++) {
        const float xt0 = xa, xt1 = xb;
        const int tn = (t < NT - 1) ? (t + 1) : (NT - 1);
        xa = x0[tn];                 // prefetch next step's x
        xb = x1[tn];

        float hp0, hp1;              // staged even-unit h values
#pragma unroll 4
        for (int jj = 0; jj < 20; jj++) {
            const int j = jg + jj;
            const ulonglong2* ri = (const ulonglong2*)(Wh + (jj)      * NH);
            const ulonglong2* rf = (const ulonglong2*)(Wh + (20 + jj) * NH);
            const ulonglong2* rg = (const ulonglong2*)(Wh + (40 + jj) * NH);
            const ulonglong2* ro = (const ulonglong2*)(Wh + (60 + jj) * NH);

            const float2 wbi = winb_s[j];
            const float2 wbf = winb_s[NH + j];
            const float2 wbg = winb_s[2 * NH + j];
            const float2 wbo = winb_s[3 * NH + j];

            // Gate bases folded into accumulator init (chain head, not tail).
            u64 ai0 = pack2(fmaf(xt0, wbi.x, wbi.y), 0.f);
            u64 af0 = pack2(fmaf(xt0, wbf.x, wbf.y), 0.f);
            u64 ag0 = pack2(fmaf(xt0, wbg.x, wbg.y), 0.f);
            u64 ao0 = pack2(fmaf(xt0, wbo.x, wbo.y), 0.f);
            u64 ai1 = pack2(fmaf(xt1, wbi.x, wbi.y), 0.f);
            u64 af1 = pack2(fmaf(xt1, wbf.x, wbf.y), 0.f);
            u64 ag1 = pack2(fmaf(xt1, wbg.x, wbg.y), 0.f);
            u64 ao1 = pack2(fmaf(xt1, wbo.x, wbo.y), 0.f);

#pragma unroll
            for (int q = 0; q < NH / 4; q++) {
                ulonglong2 wi = ri[q];
                ulonglong2 wf = rf[q];
                ulonglong2 wg = rg[q];
                ulonglong2 wo = ro[q];
                u64 ha0 = h0[2*q], hb0 = h0[2*q+1];
                u64 ha1 = h1[2*q], hb1 = h1[2*q+1];
                // 8 chains; each weight load feeds both sequences.
                ai0 = ffma2(ha0, wi.x, ai0); ai1 = ffma2(ha1, wi.x, ai1);
                af0 = ffma2(ha0, wf.x, af0); af1 = ffma2(ha1, wf.x, af1);
                ag0 = ffma2(ha0, wg.x, ag0); ag1 = ffma2(ha1, wg.x, ag1);
                ao0 = ffma2(ha0, wo.x, ao0); ao1 = ffma2(ha1, wo.x, ao1);
                ai0 = ffma2(hb0, wi.y, ai0); ai1 = ffma2(hb1, wi.y, ai1);
                af0 = ffma2(hb0, wf.y, af0); af1 = ffma2(hb1, wf.y, af1);
                ag0 = ffma2(hb0, wg.y, ag0); ag1 = ffma2(hb1, wg.y, ag1);
                ao0 = ffma2(hb0, wo.y, ao0); ao1 = ffma2(hb1, wo.y, ao1);
            }
            // Horizontal sums, then the two seqs' epilogues back-to-back so
            // their EX2/RCP latencies overlap.
            float2 p;
            p = unpack2(ai0); const float gi0 = p.x + p.y;
            p = unpack2(af0); const float gf0 = p.x + p.y;
            p = unpack2(ag0); const float gg0 = p.x + p.y;
            p = unpack2(ao0); const float go0 = p.x + p.y;
            p = unpack2(ai1); const float gi1 = p.x + p.y;
            p = unpack2(af1); const float gf1 = p.x + p.y;
            p = unpack2(ag1); const float gg1 = p.x + p.y;
            p = unpack2(ao1); const float go1 = p.x + p.y;

            const float hv0 = lstm_epilogue(gi0, gf0, gg0, go0, c0[jj]);
            const float hv1 = lstm_epilogue(gi1, gf1, gg1, go1, c1[jj]);

            if ((jj & 1) == 0) {
                hp0 = hv0; hp1 = hv1;
            } else {
                const int kp = 10 * half + (jj >> 1);
                hs[kp][2 * pair]     = make_float2(hp0, hv0);
                hs[kp][2 * pair + 1] = make_float2(hp1, hv1);
            }
        }

        __syncwarp();
#pragma unroll
        for (int k = 0; k < NH / 2; k++) {
            float2 v0 = hs[k][2 * pair];
            float2 v1 = hs[k][2 * pair + 1];
            h0[k] = pack2(v0.x, v0.y);
            h1[k] = pack2(v1.x, v1.y);
        }
        __syncwarp();
    }

    // Final head: thread tid = 2p+half outputs seq base+tid using h(half)
    float hT[NH];
#pragma unroll
    for (int k = 0; k < NH / 2; k++) {
        float2 a = unpack2(half ? h1[k] : h0[k]);
        hT[2 * k]     = a.x;
        hT[2 * k + 1] = a.y;
    }
    const long long seq = base + tid;
    float best = -3.402823466e38f;
    int bidx = 0;
#pragma unroll
    for (int cls = 0; cls < NC; cls++) {
        float acc = bfc_s[cls];
#pragma unroll
        for (int k = 0; k < NH; k++) acc = fmaf(hT[k], Wfc_s[cls * NH + k], acc);
        if (write_logits) out[seq * NC + cls] = acc;
        if (acc > best) { best = acc; bidx = cls; }
    }
    if (write_argmax) out[arg_off + seq] = (float)bidx;
}

extern "C" void kernel_launch(void* const* d_in, const int* in_sizes, int n_in,
                              void* d_out, int out_size)
{
    const float* x    = (const float*)d_in[0];
    const float* W_ih = (const float*)d_in[1];
    const float* W_hh = (const float*)d_in[2];
    const float* b_ih = (const float*)d_in[3];
    const float* b_hh = (const float*)d_in[4];
    const float* W_fc = (const float*)d_in[5];
    const float* b_fc = (const float*)d_in[6];
    float* out = (float*)d_out;

    // NOTE: no PreferredSharedMemoryCarveout — R7 showed it costs L1D with no
    // occupancy gain (3 CTAs already resident).

    const long long B = (long long)in_sizes[0] / NT;

    int write_logits = 1, write_argmax = 0;
    long long arg_off = 0;
    if ((long long)out_size >= B * (NC + 1)) {
        write_logits = 1; write_argmax = 1; arg_off = B * NC;
    } else if ((long long)out_size >= B * NC) {
        write_logits = 1; write_argmax = 0;
    } else {
        write_logits = 0; write_argmax = 1; arg_off = 0;
    }

    const int grid = (int)((B + TPB - 1) / TPB);   // 128 seqs per block
    lstm_head_kernel<<<grid, TPB>>>(x, W_ih, W_hh, b_ih, b_hh, W_fc, b_fc,
                                    out, write_logits, write_argmax, arg_off);
}

// round 12
// speedup vs baseline: 1.6426x; 1.6426x over previous
#include <cuda_runtime.h>

#define TPB 128
#define NH  40
#define NT  40
#define NG  160
#define NC  4
#define HBASE 3208   // floats per half-section: 80 rows * 40 + 8-float bank skew

typedef unsigned long long u64;

__device__ __forceinline__ u64 pack2(float lo, float hi) {
    u64 r; asm("mov.b64 %0, {%1, %2};" : "=l"(r) : "f"(lo), "f"(hi)); return r;
}
__device__ __forceinline__ float2 unpack2(u64 v) {
    float2 f; asm("mov.b64 {%0, %1}, %2;" : "=f"(f.x), "=f"(f.y) : "l"(v)); return f;
}
// Packed dual-fp32 FMA (Blackwell f32x2 pipe)
__device__ __forceinline__ u64 ffma2(u64 a, u64 b, u64 c) {
    u64 d; asm("fma.rn.f32x2 %0, %1, %2, %3;" : "=l"(d) : "l"(a), "l"(b), "l"(c)); return d;
}
__device__ __forceinline__ float rcpf(float a) {
    float r; asm("rcp.approx.f32 %0, %1;" : "=f"(r) : "f"(a)); return r;
}

// LSTM gate epilogue with batched reciprocal for the (i,f,g) trio:
// one MUFU.RCP replaces three (trio product bounded by ~3.4e9, overflow-safe).
// o-gate and tanh(c_new) keep private RCPs: 1+e^{2|c|} can reach ~5e34 and a
// batched product would flirt with fp32 overflow -> NaN tail risk.
// MUFU per call: 5 EX2 + 3 RCP (was 5 EX2 + 5 RCP).
__device__ __forceinline__ float lstm_epilogue(float gi, float gf, float gg,
                                               float go, float& c)
{
    const float t1 = __expf(-gi);
    const float t2 = __expf(-gf);
    const float t4 = __expf(-2.0f * gg);
    const float d1 = 1.0f + t1;
    const float d2 = 1.0f + t2;
    const float d4 = 1.0f + t4;
    const float e24 = d2 * d4;
    const float R  = rcpf(d1 * e24);
    const float si = R * e24;                       // sigmoid(gi)
    const float q  = R * d1;
    const float sf = q * d4;                        // sigmoid(gf)
    const float tg = fmaf(2.0f, q * d2, -1.0f);     // tanh(gg)
    const float cn = fmaf(sf, c, si * tg);
    c = cn;
    const float so = rcpf(1.0f + __expf(-go));      // sigmoid(go)
    const float th = fmaf(2.0f, rcpf(1.0f + __expf(-2.0f * cn)), -1.0f);
    return so * th;
}

__global__ __launch_bounds__(TPB, 3)
void lstm_head_kernel(const float* __restrict__ x,
                      const float* __restrict__ W_ih,
                      const float* __restrict__ W_hh,
                      const float* __restrict__ b_ih,
                      const float* __restrict__ b_hh,
                      const float* __restrict__ W_fc,
                      const float* __restrict__ b_fc,
                      float* __restrict__ out,
                      int write_logits, int write_argmax, long long arg_off)
{
    // W_hh split by unit-half: half h owns units [h*20, h*20+20).
    // Row (g, jj) of half h lives at Ws[h*HBASE + (g*20+jj)*40 .. +40).
    // HBASE skew (32B) keeps the two halves' 2-address broadcasts on disjoint banks.
    __shared__ __align__(16) float Ws[2 * HBASE];    // 25664 B
    __shared__ float2 winb_s[NG];                    // (W_ih[r], b_ih[r]+b_hh[r])
    __shared__ float  Wfc_s[NC * NH];
    __shared__ float  bfc_s[NC];
    __shared__ float2 hs[NH / 2][130];               // h staging [unit-pair][seq], padded
                                                     // (8B seq-stride: conflict-free)

    const int tid  = threadIdx.x;
    const int pair = tid >> 1;
    const int half = tid & 1;

    for (int i = tid; i < NG * NH; i += TPB) {
        int r = i / NH, k = i % NH;           // global row r = g*40 + j
        int g = r / NH, j = r % NH;
        int hh = j / 20, jj = j % 20;
        Ws[hh * HBASE + (g * 20 + jj) * NH + k] = W_hh[i];
    }
    for (int i = tid; i < NG; i += TPB)
        winb_s[i] = make_float2(W_ih[i], b_ih[i] + b_hh[i]);
    for (int i = tid; i < NC * NH; i += TPB) Wfc_s[i] = W_fc[i];
    if (tid < NC) bfc_s[tid] = b_fc[tid];
    __syncthreads();

    const long long base = (long long)blockIdx.x * TPB;  // 128 seqs per block
    const float* __restrict__ x0 = x + (base + 2 * pair) * NT;      // seq 2p
    const float* __restrict__ x1 = x0 + NT;                          // seq 2p+1

    const float* Wh = Ws + half * HBASE;
    const int jg = half * 20;     // first owned global unit

    u64 h0[NH / 2], h1[NH / 2];   // full packed h for seqs 2p, 2p+1
    float c0[20], c1[20];         // cell state, my 20 units only
#pragma unroll
    for (int k = 0; k < NH / 2; k++) { h0[k] = 0ULL; h1[k] = 0ULL; }
#pragma unroll
    for (int k = 0; k < 20; k++) { c0[k] = 0.0f; c1[k] = 0.0f; }

    float xa = x0[0];
    float xb = x1[0];

#pragma unroll 1
    for (int t = 0; t < NT; t++) {
        const float xt0 = xa, xt1 = xb;
        const int tn = (t < NT - 1) ? (t + 1) : (NT - 1);
        xa = x0[tn];                 // prefetch next step's x
        xb = x1[tn];

        float hp0, hp1;              // staged even-unit h values
#pragma unroll 4
        for (int jj = 0; jj < 20; jj++) {
            const int j = jg + jj;
            const ulonglong2* ri = (const ulonglong2*)(Wh + (jj)      * NH);
            const ulonglong2* rf = (const ulonglong2*)(Wh + (20 + jj) * NH);
            const ulonglong2* rg = (const ulonglong2*)(Wh + (40 + jj) * NH);
            const ulonglong2* ro = (const ulonglong2*)(Wh + (60 + jj) * NH);

            const float2 wbi = winb_s[j];
            const float2 wbf = winb_s[NH + j];
            const float2 wbg = winb_s[2 * NH + j];
            const float2 wbo = winb_s[3 * NH + j];

            // Gate bases folded into accumulator init (chain head, not tail).
            u64 ai0 = pack2(fmaf(xt0, wbi.x, wbi.y), 0.f);
            u64 af0 = pack2(fmaf(xt0, wbf.x, wbf.y), 0.f);
            u64 ag0 = pack2(fmaf(xt0, wbg.x, wbg.y), 0.f);
            u64 ao0 = pack2(fmaf(xt0, wbo.x, wbo.y), 0.f);
            u64 ai1 = pack2(fmaf(xt1, wbi.x, wbi.y), 0.f);
            u64 af1 = pack2(fmaf(xt1, wbf.x, wbf.y), 0.f);
            u64 ag1 = pack2(fmaf(xt1, wbg.x, wbg.y), 0.f);
            u64 ao1 = pack2(fmaf(xt1, wbo.x, wbo.y), 0.f);

#pragma unroll
            for (int q = 0; q < NH / 4; q++) {
                ulonglong2 wi = ri[q];
                ulonglong2 wf = rf[q];
                ulonglong2 wg = rg[q];
                ulonglong2 wo = ro[q];
                u64 ha0 = h0[2*q], hb0 = h0[2*q+1];
                u64 ha1 = h1[2*q], hb1 = h1[2*q+1];
                // 8 chains; each weight load feeds both sequences.
                ai0 = ffma2(ha0, wi.x, ai0); ai1 = ffma2(ha1, wi.x, ai1);
                af0 = ffma2(ha0, wf.x, af0); af1 = ffma2(ha1, wf.x, af1);
                ag0 = ffma2(ha0, wg.x, ag0); ag1 = ffma2(ha1, wg.x, ag1);
                ao0 = ffma2(ha0, wo.x, ao0); ao1 = ffma2(ha1, wo.x, ao1);
                ai0 = ffma2(hb0, wi.y, ai0); ai1 = ffma2(hb1, wi.y, ai1);
                af0 = ffma2(hb0, wf.y, af0); af1 = ffma2(hb1, wf.y, af1);
                ag0 = ffma2(hb0, wg.y, ag0); ag1 = ffma2(hb1, wg.y, ag1);
                ao0 = ffma2(hb0, wo.y, ao0); ao1 = ffma2(hb1, wo.y, ao1);
            }
            // Horizontal sums, then the two seqs' epilogues back-to-back so
            // their EX2/RCP latencies overlap.
            float2 p;
            p = unpack2(ai0); const float gi0 = p.x + p.y;
            p = unpack2(af0); const float gf0 = p.x + p.y;
            p = unpack2(ag0); const float gg0 = p.x + p.y;
            p = unpack2(ao0); const float go0 = p.x + p.y;
            p = unpack2(ai1); const float gi1 = p.x + p.y;
            p = unpack2(af1); const float gf1 = p.x + p.y;
            p = unpack2(ag1); const float gg1 = p.x + p.y;
            p = unpack2(ao1); const float go1 = p.x + p.y;

            const float hv0 = lstm_epilogue(gi0, gf0, gg0, go0, c0[jj]);
            const float hv1 = lstm_epilogue(gi1, gf1, gg1, go1, c1[jj]);

            if ((jj & 1) == 0) {
                hp0 = hv0; hp1 = hv1;
            } else {
                const int kp = 10 * half + (jj >> 1);
                hs[kp][2 * pair]     = make_float2(hp0, hv0);
                hs[kp][2 * pair + 1] = make_float2(hp1, hv1);
            }
        }

        __syncwarp();
#pragma unroll
        for (int k = 0; k < NH / 2; k++) {
            float2 v0 = hs[k][2 * pair];
            float2 v1 = hs[k][2 * pair + 1];
            h0[k] = pack2(v0.x, v0.y);
            h1[k] = pack2(v1.x, v1.y);
        }
        __syncwarp();
    }

    // Final head: thread tid = 2p+half outputs seq base+tid using h(half)
    float hT[NH];
#pragma unroll
    for (int k = 0; k < NH / 2; k++) {
        float2 a = unpack2(half ? h1[k] : h0[k]);
        hT[2 * k]     = a.x;
        hT[2 * k + 1] = a.y;
    }
    const long long seq = base + tid;
    float best = -3.402823466e38f;
    int bidx = 0;
#pragma unroll
    for (int cls = 0; cls < NC; cls++) {
        float acc = bfc_s[cls];
#pragma unroll
        for (int k = 0; k < NH; k++) acc = fmaf(hT[k], Wfc_s[cls * NH + k], acc);
        if (write_logits) out[seq * NC + cls] = acc;
        if (acc > best) { best = acc; bidx = cls; }
    }
    if (write_argmax) out[arg_off + seq] = (float)bidx;
}

extern "C" void kernel_launch(void* const* d_in, const int* in_sizes, int n_in,
                              void* d_out, int out_size)
{
    const float* x    = (const float*)d_in[0];
    const float* W_ih = (const float*)d_in[1];
    const float* W_hh = (const float*)d_in[2];
    const float* b_ih = (const float*)d_in[3];
    const float* b_hh = (const float*)d_in[4];
    const float* W_fc = (const float*)d_in[5];
    const float* b_fc = (const float*)d_in[6];
    float* out = (float*)d_out;

    // NOTE: no PreferredSharedMemoryCarveout — costs L1D, no occupancy gain.

    const long long B = (long long)in_sizes[0] / NT;

    int write_logits = 1, write_argmax = 0;
    long long arg_off = 0;
    if ((long long)out_size >= B * (NC + 1)) {
        write_logits = 1; write_argmax = 1; arg_off = B * NC;
    } else if ((long long)out_size >= B * NC) {
        write_logits = 1; write_argmax = 0;
    } else {
        write_logits = 0; write_argmax = 1; arg_off = 0;
    }

    const int grid = (int)((B + TPB - 1) / TPB);   // 128 seqs per block
    lstm_head_kernel<<<grid, TPB>>>(x, W_ih, W_hh, b_ih, b_hh, W_fc, b_fc,
                                    out, write_logits, write_argmax, arg_off);
}

// round 13
// speedup vs baseline: 1.7172x; 1.0454x over previous
#include <cuda_runtime.h>

#define TPB 128
#define NH  40
#define NT  40
#define NG  160
#define NC  4
#define HBASE 3208   // floats per half-section: 80 rows * 40 + 8-float bank skew

typedef unsigned long long u64;

__device__ __forceinline__ u64 pack2(float lo, float hi) {
    u64 r; asm("mov.b64 %0, {%1, %2};" : "=l"(r) : "f"(lo), "f"(hi)); return r;
}
__device__ __forceinline__ float2 unpack2(u64 v) {
    float2 f; asm("mov.b64 {%0, %1}, %2;" : "=f"(f.x), "=f"(f.y) : "l"(v)); return f;
}
// Packed dual-fp32 FMA (Blackwell f32x2 pipe)
__device__ __forceinline__ u64 ffma2(u64 a, u64 b, u64 c) {
    u64 d; asm("fma.rn.f32x2 %0, %1, %2, %3;" : "=l"(d) : "l"(a), "l"(b), "l"(c)); return d;
}
__device__ __forceinline__ float sigf(float z) {
    return __fdividef(1.0f, 1.0f + __expf(-z));
}
__device__ __forceinline__ float tanh_fast(float z) {
    return fmaf(2.0f, sigf(2.0f * z), -1.0f);
}

__global__ __launch_bounds__(TPB, 3)
void lstm_head_kernel(const float* __restrict__ x,
                      const float* __restrict__ W_ih,
                      const float* __restrict__ W_hh,
                      const float* __restrict__ b_ih,
                      const float* __restrict__ b_hh,
                      const float* __restrict__ W_fc,
                      const float* __restrict__ b_fc,
                      float* __restrict__ out,
                      int write_logits, int write_argmax, long long arg_off)
{
    // W_hh split by unit-half: half h owns units [h*20, h*20+20).
    // Row (g, jj) of half h lives at Ws[h*HBASE + (g*20+jj)*40 .. +40).
    // HBASE skew (32B) keeps the two halves' 2-address broadcasts on disjoint banks.
    __shared__ __align__(16) float Ws[2 * HBASE];    // 25664 B
    __shared__ float2 winb_s[NG];                    // (W_ih[r], b_ih[r]+b_hh[r])
    __shared__ float  Wfc_s[NC * NH];
    __shared__ float  bfc_s[NC];
    __shared__ float2 hs[NH / 2][130];               // h staging [unit-pair][seq], padded
                                                     // (8B seq-stride: conflict-free)

    const int tid  = threadIdx.x;
    const int pair = tid >> 1;
    const int half = tid & 1;

    for (int i = tid; i < NG * NH; i += TPB) {
        int r = i / NH, k = i % NH;           // global row r = g*40 + j
        int g = r / NH, j = r % NH;
        int hh = j / 20, jj = j % 20;
        Ws[hh * HBASE + (g * 20 + jj) * NH + k] = W_hh[i];
    }
    for (int i = tid; i < NG; i += TPB)
        winb_s[i] = make_float2(W_ih[i], b_ih[i] + b_hh[i]);
    for (int i = tid; i < NC * NH; i += TPB) Wfc_s[i] = W_fc[i];
    if (tid < NC) bfc_s[tid] = b_fc[tid];
    __syncthreads();

    const long long base = (long long)blockIdx.x * TPB;  // 128 seqs per block
    const float* __restrict__ x0 = x + (base + 2 * pair) * NT;      // seq 2p
    const float* __restrict__ x1 = x0 + NT;                          // seq 2p+1

    const float* Wh = Ws + half * HBASE;
    const int jg = half * 20;     // first owned global unit

    u64 h0[NH / 2], h1[NH / 2];   // full packed h for seqs 2p, 2p+1
    float c0[20], c1[20];         // cell state, my 20 units only
#pragma unroll
    for (int k = 0; k < NH / 2; k++) { h0[k] = 0ULL; h1[k] = 0ULL; }
#pragma unroll
    for (int k = 0; k < 20; k++) { c0[k] = 0.0f; c1[k] = 0.0f; }

    float xa = x0[0];
    float xb = x1[0];

#pragma unroll 1
    for (int t = 0; t < NT; t++) {
        const float xt0 = xa, xt1 = xb;
        const int tn = (t < NT - 1) ? (t + 1) : (NT - 1);
        xa = x0[tn];                 // prefetch next step's x
        xb = x1[tn];

        float hp0, hp1;              // staged even-unit h values
        float pcn0, pcn1, pgo0, pgo1; // deferred tail state of unit jj-1

#pragma unroll 4
        for (int jj = 0; jj < 20; jj++) {
            const int j = jg + jj;
            const ulonglong2* ri = (const ulonglong2*)(Wh + (jj)      * NH);
            const ulonglong2* rf = (const ulonglong2*)(Wh + (20 + jj) * NH);
            const ulonglong2* rg = (const ulonglong2*)(Wh + (40 + jj) * NH);
            const ulonglong2* ro = (const ulonglong2*)(Wh + (60 + jj) * NH);

            const float2 wbi = winb_s[j];
            const float2 wbf = winb_s[NH + j];
            const float2 wbg = winb_s[2 * NH + j];
            const float2 wbo = winb_s[3 * NH + j];

            // Gate bases folded into accumulator init (chain head, not tail).
            u64 ai0 = pack2(fmaf(xt0, wbi.x, wbi.y), 0.f);
            u64 af0 = pack2(fmaf(xt0, wbf.x, wbf.y), 0.f);
            u64 ag0 = pack2(fmaf(xt0, wbg.x, wbg.y), 0.f);
            u64 ao0 = pack2(fmaf(xt0, wbo.x, wbo.y), 0.f);
            u64 ai1 = pack2(fmaf(xt1, wbi.x, wbi.y), 0.f);
            u64 af1 = pack2(fmaf(xt1, wbf.x, wbf.y), 0.f);
            u64 ag1 = pack2(fmaf(xt1, wbg.x, wbg.y), 0.f);
            u64 ao1 = pack2(fmaf(xt1, wbo.x, wbo.y), 0.f);

#pragma unroll
            for (int q = 0; q < NH / 4; q++) {
                ulonglong2 wi = ri[q];
                ulonglong2 wf = rf[q];
                ulonglong2 wg = rg[q];
                ulonglong2 wo = ro[q];
                u64 ha0 = h0[2*q], hb0 = h0[2*q+1];
                u64 ha1 = h1[2*q], hb1 = h1[2*q+1];
                // 8 chains; each weight load feeds both sequences.
                ai0 = ffma2(ha0, wi.x, ai0); ai1 = ffma2(ha1, wi.x, ai1);
                af0 = ffma2(ha0, wf.x, af0); af1 = ffma2(ha1, wf.x, af1);
                ag0 = ffma2(ha0, wg.x, ag0); ag1 = ffma2(ha1, wg.x, ag1);
                ao0 = ffma2(ha0, wo.x, ao0); ao1 = ffma2(ha1, wo.x, ao1);
                ai0 = ffma2(hb0, wi.y, ai0); ai1 = ffma2(hb1, wi.y, ai1);
                af0 = ffma2(hb0, wf.y, af0); af1 = ffma2(hb1, wf.y, af1);
                ag0 = ffma2(hb0, wg.y, ag0); ag1 = ffma2(hb1, wg.y, ag1);
                ao0 = ffma2(hb0, wo.y, ao0); ao1 = ffma2(hb1, wo.y, ao1);
            }

            // ── Deferred tail of unit jj-1: two dependent MUFU chains
            // (sigmoid(go), tanh(cn)) now overlap THIS unit's FFMA2 block.
            if (jj > 0) {
                const float hvp0 = sigf(pgo0) * tanh_fast(pcn0);
                const float hvp1 = sigf(pgo1) * tanh_fast(pcn1);
                const int ju = jj - 1;
                if ((ju & 1) == 0) {
                    hp0 = hvp0; hp1 = hvp1;
                } else {
                    const int kp = 10 * half + (ju >> 1);
                    hs[kp][2 * pair]     = make_float2(hp0, hvp0);
                    hs[kp][2 * pair + 1] = make_float2(hp1, hvp1);
                }
            }

            // ── Head of unit jj: sums + i/f/g activations + cell update.
            float2 p;
            p = unpack2(ai0); const float gi0 = p.x + p.y;
            p = unpack2(af0); const float gf0 = p.x + p.y;
            p = unpack2(ag0); const float gg0 = p.x + p.y;
            p = unpack2(ao0); const float go0 = p.x + p.y;
            p = unpack2(ai1); const float gi1 = p.x + p.y;
            p = unpack2(af1); const float gf1 = p.x + p.y;
            p = unpack2(ag1); const float gg1 = p.x + p.y;
            p = unpack2(ao1); const float go1 = p.x + p.y;

            const float cn0 = fmaf(sigf(gf0), c0[jj], sigf(gi0) * tanh_fast(gg0));
            const float cn1 = fmaf(sigf(gf1), c1[jj], sigf(gi1) * tanh_fast(gg1));
            c0[jj] = cn0;
            c1[jj] = cn1;
            pcn0 = cn0; pcn1 = cn1;
            pgo0 = go0; pgo1 = go1;
        }

        // Tail of the last unit (jj = 19, odd -> completes a staged pair).
        {
            const float hvp0 = sigf(pgo0) * tanh_fast(pcn0);
            const float hvp1 = sigf(pgo1) * tanh_fast(pcn1);
            const int kp = 10 * half + 9;
            hs[kp][2 * pair]     = make_float2(hp0, hvp0);
            hs[kp][2 * pair + 1] = make_float2(hp1, hvp1);
        }

        __syncwarp();
#pragma unroll
        for (int k = 0; k < NH / 2; k++) {
            float2 v0 = hs[k][2 * pair];
            float2 v1 = hs[k][2 * pair + 1];
            h0[k] = pack2(v0.x, v0.y);
            h1[k] = pack2(v1.x, v1.y);
        }
        __syncwarp();
    }

    // Final head: thread tid = 2p+half outputs seq base+tid using h(half)
    float hT[NH];
#pragma unroll
    for (int k = 0; k < NH / 2; k++) {
        float2 a = unpack2(half ? h1[k] : h0[k]);
        hT[2 * k]     = a.x;
        hT[2 * k + 1] = a.y;
    }
    const long long seq = base + tid;
    float best = -3.402823466e38f;
    int bidx = 0;
#pragma unroll
    for (int cls = 0; cls < NC; cls++) {
        float acc = bfc_s[cls];
#pragma unroll
        for (int k = 0; k < NH; k++) acc = fmaf(hT[k], Wfc_s[cls * NH + k], acc);
        if (write_logits) out[seq * NC + cls] = acc;
        if (acc > best) { best = acc; bidx = cls; }
    }
    if (write_argmax) out[arg_off + seq] = (float)bidx;
}

extern "C" void kernel_launch(void* const* d_in, const int* in_sizes, int n_in,
                              void* d_out, int out_size)
{
    const float* x    = (const float*)d_in[0];
    const float* W_ih = (const float*)d_in[1];
    const float* W_hh = (const float*)d_in[2];
    const float* b_ih = (const float*)d_in[3];
    const float* b_hh = (const float*)d_in[4];
    const float* W_fc = (const float*)d_in[5];
    const float* b_fc = (const float*)d_in[6];
    float* out = (float*)d_out;

    // NOTE: no PreferredSharedMemoryCarveout — costs L1D, no occupancy gain.

    const long long B = (long long)in_sizes[0] / NT;

    int write_logits = 1, write_argmax = 0;
    long long arg_off = 0;
    if ((long long)out_size >= B * (NC + 1)) {
        write_logits = 1; write_argmax = 1; arg_off = B * NC;
    } else if ((long long)out_size >= B * NC) {
        write_logits = 1; write_argmax = 0;
    } else {
        write_logits = 0; write_argmax = 1; arg_off = 0;
    }

    const int grid = (int)((B + TPB - 1) / TPB);   // 128 seqs per block
    lstm_head_kernel<<<grid, TPB>>>(x, W_ih, W_hh, b_ih, b_hh, W_fc, b_fc,
                                    out, write_logits, write_argmax, arg_off);
}

// round 14
// speedup vs baseline: 1.7445x; 1.0159x over previous
#include <cuda_runtime.h>

#define TPB 128
#define NH  40
#define NT  40
#define NG  160
#define NC  4
#define HBASE 3208   // floats per half-section: 80 rows * 40 + 8-float bank skew

typedef unsigned long long u64;

__device__ __forceinline__ u64 pack2(float lo, float hi) {
    u64 r; asm("mov.b64 %0, {%1, %2};" : "=l"(r) : "f"(lo), "f"(hi)); return r;
}
__device__ __forceinline__ float2 unpack2(u64 v) {
    float2 f; asm("mov.b64 {%0, %1}, %2;" : "=f"(f.x), "=f"(f.y) : "l"(v)); return f;
}
// Packed dual-fp32 FMA (Blackwell f32x2 pipe)
__device__ __forceinline__ u64 ffma2(u64 a, u64 b, u64 c) {
    u64 d; asm("fma.rn.f32x2 %0, %1, %2, %3;" : "=l"(d) : "l"(a), "l"(b), "l"(c)); return d;
}
__device__ __forceinline__ float sigf(float z) {
    return __fdividef(1.0f, 1.0f + __expf(-z));
}
__device__ __forceinline__ float tanh_fast(float z) {
    return fmaf(2.0f, sigf(2.0f * z), -1.0f);
}

__global__ __launch_bounds__(TPB, 3)
void lstm_head_kernel(const float* __restrict__ x,
                      const float* __restrict__ W_ih,
                      const float* __restrict__ W_hh,
                      const float* __restrict__ b_ih,
                      const float* __restrict__ b_hh,
                      const float* __restrict__ W_fc,
                      const float* __restrict__ b_fc,
                      float* __restrict__ out,
                      int write_logits, int write_argmax, long long arg_off)
{
    // W_hh split by unit-half: half h owns units [h*20, h*20+20).
    // Row (g, jj) of half h lives at Ws[h*HBASE + (g*20+jj)*40 .. +40).
    // HBASE skew (32B) keeps the two halves' 2-address broadcasts on disjoint banks.
    __shared__ __align__(16) float Ws[2 * HBASE];    // 25664 B
    __shared__ float2 winb_s[NG];                    // (W_ih[r], b_ih[r]+b_hh[r])
    __shared__ float  Wfc_s[NC * NH];
    __shared__ float  bfc_s[NC];
    __shared__ float2 hs[NH / 2][130];               // h staging [unit-pair][seq], padded
                                                     // (8B seq-stride: conflict-free)

    const int tid  = threadIdx.x;
    const int pair = tid >> 1;
    const int half = tid & 1;

    for (int i = tid; i < NG * NH; i += TPB) {
        int r = i / NH, k = i % NH;           // global row r = g*40 + j
        int g = r / NH, j = r % NH;
        int hh = j / 20, jj = j % 20;
        Ws[hh * HBASE + (g * 20 + jj) * NH + k] = W_hh[i];
    }
    for (int i = tid; i < NG; i += TPB)
        winb_s[i] = make_float2(W_ih[i], b_ih[i] + b_hh[i]);
    for (int i = tid; i < NC * NH; i += TPB) Wfc_s[i] = W_fc[i];
    if (tid < NC) bfc_s[tid] = b_fc[tid];
    __syncthreads();

    const long long base = (long long)blockIdx.x * TPB;  // 128 seqs per block
    const float* __restrict__ x0 = x + (base + 2 * pair) * NT;      // seq 2p
    const float* __restrict__ x1 = x0 + NT;                          // seq 2p+1

    const float* Wh = Ws + half * HBASE;
    const int jg = half * 20;     // first owned global unit

    u64 h0[NH / 2], h1[NH / 2];   // full packed h for seqs 2p, 2p+1
    float c0[20], c1[20];         // cell state, my 20 units only
#pragma unroll
    for (int k = 0; k < NH / 2; k++) { h0[k] = 0ULL; h1[k] = 0ULL; }
#pragma unroll
    for (int k = 0; k < 20; k++) { c0[k] = 0.0f; c1[k] = 0.0f; }

    float xa = x0[0];
    float xb = x1[0];

#pragma unroll 1
    for (int t = 0; t < NT; t++) {
        const float xt0 = xa, xt1 = xb;
        const int tn = (t < NT - 1) ? (t + 1) : (NT - 1);
        xa = x0[tn];                 // prefetch next step's x
        xb = x1[tn];

        float hp0, hp1;              // staged even-unit h values
#pragma unroll 4
        for (int jj = 0; jj < 20; jj++) {
            const int j = jg + jj;
            const ulonglong2* ri = (const ulonglong2*)(Wh + (jj)      * NH);
            const ulonglong2* rf = (const ulonglong2*)(Wh + (20 + jj) * NH);
            const ulonglong2* rg = (const ulonglong2*)(Wh + (40 + jj) * NH);
            const ulonglong2* ro = (const ulonglong2*)(Wh + (60 + jj) * NH);

            const float2 wbi = winb_s[j];
            const float2 wbf = winb_s[NH + j];
            const float2 wbg = winb_s[2 * NH + j];
            const float2 wbo = winb_s[3 * NH + j];

            // Gate bases folded into accumulator init (chain head, not tail).
            u64 ai0 = pack2(fmaf(xt0, wbi.x, wbi.y), 0.f);
            u64 af0 = pack2(fmaf(xt0, wbf.x, wbf.y), 0.f);
            u64 ag0 = pack2(fmaf(xt0, wbg.x, wbg.y), 0.f);
            u64 ao0 = pack2(fmaf(xt0, wbo.x, wbo.y), 0.f);
            u64 ai1 = pack2(fmaf(xt1, wbi.x, wbi.y), 0.f);
            u64 af1 = pack2(fmaf(xt1, wbf.x, wbf.y), 0.f);
            u64 ag1 = pack2(fmaf(xt1, wbg.x, wbg.y), 0.f);
            u64 ao1 = pack2(fmaf(xt1, wbo.x, wbo.y), 0.f);

#pragma unroll
            for (int q = 0; q < NH / 4; q++) {
                ulonglong2 wi = ri[q];
                ulonglong2 wf = rf[q];
                ulonglong2 wg = rg[q];
                ulonglong2 wo = ro[q];
                u64 ha0 = h0[2*q], hb0 = h0[2*q+1];
                u64 ha1 = h1[2*q], hb1 = h1[2*q+1];
                // 8 chains; each weight load feeds both sequences.
                ai0 = ffma2(ha0, wi.x, ai0); ai1 = ffma2(ha1, wi.x, ai1);
                af0 = ffma2(ha0, wf.x, af0); af1 = ffma2(ha1, wf.x, af1);
                ag0 = ffma2(ha0, wg.x, ag0); ag1 = ffma2(ha1, wg.x, ag1);
                ao0 = ffma2(ha0, wo.x, ao0); ao1 = ffma2(ha1, wo.x, ao1);
                ai0 = ffma2(hb0, wi.y, ai0); ai1 = ffma2(hb1, wi.y, ai1);
                af0 = ffma2(hb0, wf.y, af0); af1 = ffma2(hb1, wf.y, af1);
                ag0 = ffma2(hb0, wg.y, ag0); ag1 = ffma2(hb1, wg.y, ag1);
                ao0 = ffma2(hb0, wo.y, ao0); ao1 = ffma2(hb1, wo.y, ao1);
            }
            // All 8 horizontal sums first, then activation chains grouped so
            // their MUFU latencies overlap (and across 4 unrolled jj's).
            float2 p;
            p = unpack2(ai0); const float gi0 = p.x + p.y;
            p = unpack2(af0); const float gf0 = p.x + p.y;
            p = unpack2(ag0); const float gg0 = p.x + p.y;
            p = unpack2(ao0); const float go0 = p.x + p.y;
            p = unpack2(ai1); const float gi1 = p.x + p.y;
            p = unpack2(af1); const float gf1 = p.x + p.y;
            p = unpack2(ag1); const float gg1 = p.x + p.y;
            p = unpack2(ao1); const float go1 = p.x + p.y;

            const float si0 = sigf(gi0), si1 = sigf(gi1);
            const float sf0 = sigf(gf0), sf1 = sigf(gf1);
            const float tg0 = tanh_fast(gg0), tg1 = tanh_fast(gg1);
            const float so0 = sigf(go0), so1 = sigf(go1);

            const float cn0 = fmaf(sf0, c0[jj], si0 * tg0);
            const float cn1 = fmaf(sf1, c1[jj], si1 * tg1);
            c0[jj] = cn0;
            c1[jj] = cn1;
            const float hv0 = so0 * tanh_fast(cn0);
            const float hv1 = so1 * tanh_fast(cn1);

            if ((jj & 1) == 0) {
                hp0 = hv0; hp1 = hv1;
            } else {
                const int kp = 10 * half + (jj >> 1);
                hs[kp][2 * pair]     = make_float2(hp0, hv0);
                hs[kp][2 * pair + 1] = make_float2(hp1, hv1);
            }
        }

        __syncwarp();
#pragma unroll
        for (int k = 0; k < NH / 2; k++) {
            float2 v0 = hs[k][2 * pair];
            float2 v1 = hs[k][2 * pair + 1];
            h0[k] = pack2(v0.x, v0.y);
            h1[k] = pack2(v1.x, v1.y);
        }
        __syncwarp();
    }

    // Final head: thread tid = 2p+half outputs seq base+tid using h(half)
    float hT[NH];
#pragma unroll
    for (int k = 0; k < NH / 2; k++) {
        float2 a = unpack2(half ? h1[k] : h0[k]);
        hT[2 * k]     = a.x;
        hT[2 * k + 1] = a.y;
    }
    const long long seq = base + tid;
    float best = -3.402823466e38f;
    int bidx = 0;
#pragma unroll
    for (int cls = 0; cls < NC; cls++) {
        float acc = bfc_s[cls];
#pragma unroll
        for (int k = 0; k < NH; k++) acc = fmaf(hT[k], Wfc_s[cls * NH + k], acc);
        if (write_logits) out[seq * NC + cls] = acc;
        if (acc > best) { best = acc; bidx = cls; }
    }
    if (write_argmax) out[arg_off + seq] = (float)bidx;
}

extern "C" void kernel_launch(void* const* d_in, const int* in_sizes, int n_in,
                              void* d_out, int out_size)
{
    const float* x    = (const float*)d_in[0];
    const float* W_ih = (const float*)d_in[1];
    const float* W_hh = (const float*)d_in[2];
    const float* b_ih = (const float*)d_in[3];
    const float* b_hh = (const float*)d_in[4];
    const float* W_fc = (const float*)d_in[5];
    const float* b_fc = (const float*)d_in[6];
    float* out = (float*)d_out;

    // NOTE: no PreferredSharedMemoryCarveout — costs L1D, no occupancy gain.

    const long long B = (long long)in_sizes[0] / NT;

    int write_logits = 1, write_argmax = 0;
    long long arg_off = 0;
    if ((long long)out_size >= B * (NC + 1)) {
        write_logits = 1; write_argmax = 1; arg_off = B * NC;
    } else if ((long long)out_size >= B * NC) {
        write_logits = 1; write_argmax = 0;
    } else {
        write_logits = 0; write_argmax = 1; arg_off = 0;
    }

    const int grid = (int)((B + TPB - 1) / TPB);   // 128 seqs per block
    lstm_head_kernel<<<grid, TPB>>>(x, W_ih, W_hh, b_ih, b_hh, W_fc, b_fc,
                                    out, write_logits, write_argmax, arg_off);
}

// round 15
// speedup vs baseline: 1.7468x; 1.0013x over previous
#include <cuda_runtime.h>

#define TPB 128
#define NH  40
#define NT  40
#define NG  160
#define NC  4
#define HBASE 3208   // floats per half-section: 80 rows * 40 + 8-float bank skew

typedef unsigned long long u64;

__device__ __forceinline__ u64 pack2(float lo, float hi) {
    u64 r; asm("mov.b64 %0, {%1, %2};" : "=l"(r) : "f"(lo), "f"(hi)); return r;
}
__device__ __forceinline__ float2 unpack2(u64 v) {
    float2 f; asm("mov.b64 {%0, %1}, %2;" : "=f"(f.x), "=f"(f.y) : "l"(v)); return f;
}
// Packed dual-fp32 FMA (Blackwell f32x2 pipe)
__device__ __forceinline__ u64 ffma2(u64 a, u64 b, u64 c) {
    u64 d; asm("fma.rn.f32x2 %0, %1, %2, %3;" : "=l"(d) : "l"(a), "l"(b), "l"(c)); return d;
}
__device__ __forceinline__ float sigf(float z) {
    return __fdividef(1.0f, 1.0f + __expf(-z));
}
__device__ __forceinline__ float tanh_fast(float z) {
    return fmaf(2.0f, sigf(2.0f * z), -1.0f);
}

__global__ __launch_bounds__(TPB, 3)
void lstm_head_kernel(const float* __restrict__ x,
                      const float* __restrict__ W_ih,
                      const float* __restrict__ W_hh,
                      const float* __restrict__ b_ih,
                      const float* __restrict__ b_hh,
                      const float* __restrict__ W_fc,
                      const float* __restrict__ b_fc,
                      float* __restrict__ out,
                      int write_logits, int write_argmax, long long arg_off)
{
    // W_hh split by unit-half: half h owns units [h*20, h*20+20).
    // Row (g, jj) of half h lives at Ws[h*HBASE + (g*20+jj)*40 .. +40).
    // HBASE skew (32B) keeps the two halves' 2-address broadcasts on disjoint banks.
    __shared__ __align__(16) float Ws[2 * HBASE];    // 25664 B
    __shared__ float2 winb_s[NG];                    // (W_ih[r], b_ih[r]+b_hh[r])
    __shared__ float  Wfc_s[NC * NH];
    __shared__ float  bfc_s[NC];
    __shared__ float2 hs[NH / 2][130];               // h staging [unit-pair][seq], padded
                                                     // (8B seq-stride: conflict-free)

    const int tid  = threadIdx.x;
    const int pair = tid >> 1;
    const int half = tid & 1;

    for (int i = tid; i < NG * NH; i += TPB) {
        int r = i / NH, k = i % NH;           // global row r = g*40 + j
        int g = r / NH, j = r % NH;
        int hh = j / 20, jj = j % 20;
        Ws[hh * HBASE + (g * 20 + jj) * NH + k] = W_hh[i];
    }
    for (int i = tid; i < NG; i += TPB)
        winb_s[i] = make_float2(W_ih[i], b_ih[i] + b_hh[i]);
    for (int i = tid; i < NC * NH; i += TPB) Wfc_s[i] = W_fc[i];
    if (tid < NC) bfc_s[tid] = b_fc[tid];
    __syncthreads();

    const long long base = (long long)blockIdx.x * TPB;  // 128 seqs per block
    const float* __restrict__ x0 = x + (base + 2 * pair) * NT;      // seq 2p
    const float* __restrict__ x1 = x0 + NT;                          // seq 2p+1

    const float* Wh = Ws + half * HBASE;
    const int jg = half * 20;     // first owned global unit

    u64 h0[NH / 2], h1[NH / 2];   // full packed h for seqs 2p, 2p+1
    float c0[20], c1[20];         // cell state, my 20 units only
#pragma unroll
    for (int k = 0; k < NH / 2; k++) { h0[k] = 0ULL; h1[k] = 0ULL; }
#pragma unroll
    for (int k = 0; k < 20; k++) { c0[k] = 0.0f; c1[k] = 0.0f; }

    float xa = x0[0];
    float xb = x1[0];

#pragma unroll 1
    for (int t = 0; t < NT; t++) {
        const float xt0 = xa, xt1 = xb;
        const int tn = (t < NT - 1) ? (t + 1) : (NT - 1);
        xa = x0[tn];                 // prefetch next step's x
        xb = x1[tn];

        float hp0, hp1;              // staged even-unit h values
#pragma unroll 4
        for (int jj = 0; jj < 20; jj++) {
            const int j = jg + jj;
            const ulonglong2* ri = (const ulonglong2*)(Wh + (jj)      * NH);
            const ulonglong2* rf = (const ulonglong2*)(Wh + (20 + jj) * NH);
            const ulonglong2* rg = (const ulonglong2*)(Wh + (40 + jj) * NH);
            const ulonglong2* ro = (const ulonglong2*)(Wh + (60 + jj) * NH);

            const float2 wbi = winb_s[j];
            const float2 wbf = winb_s[NH + j];
            const float2 wbg = winb_s[2 * NH + j];
            const float2 wbo = winb_s[3 * NH + j];

            // Gate bases folded into accumulator init (chain head, not tail).
            u64 ai0 = pack2(fmaf(xt0, wbi.x, wbi.y), 0.f);
            u64 af0 = pack2(fmaf(xt0, wbf.x, wbf.y), 0.f);
            u64 ag0 = pack2(fmaf(xt0, wbg.x, wbg.y), 0.f);
            u64 ao0 = pack2(fmaf(xt0, wbo.x, wbo.y), 0.f);
            u64 ai1 = pack2(fmaf(xt1, wbi.x, wbi.y), 0.f);
            u64 af1 = pack2(fmaf(xt1, wbf.x, wbf.y), 0.f);
            u64 ag1 = pack2(fmaf(xt1, wbg.x, wbg.y), 0.f);
            u64 ao1 = pack2(fmaf(xt1, wbo.x, wbo.y), 0.f);

#pragma unroll
            for (int q = 0; q < NH / 4; q++) {
                ulonglong2 wi = ri[q];
                ulonglong2 wf = rf[q];
                ulonglong2 wg = rg[q];
                ulonglong2 wo = ro[q];
                u64 ha0 = h0[2*q], hb0 = h0[2*q+1];
                u64 ha1 = h1[2*q], hb1 = h1[2*q+1];
                // 8 chains; each weight load feeds both sequences.
                ai0 = ffma2(ha0, wi.x, ai0); ai1 = ffma2(ha1, wi.x, ai1);
                af0 = ffma2(ha0, wf.x, af0); af1 = ffma2(ha1, wf.x, af1);
                ag0 = ffma2(ha0, wg.x, ag0); ag1 = ffma2(ha1, wg.x, ag1);
                ao0 = ffma2(ha0, wo.x, ao0); ao1 = ffma2(ha1, wo.x, ao1);
                ai0 = ffma2(hb0, wi.y, ai0); ai1 = ffma2(hb1, wi.y, ai1);
                af0 = ffma2(hb0, wf.y, af0); af1 = ffma2(hb1, wf.y, af1);
                ag0 = ffma2(hb0, wg.y, ag0); ag1 = ffma2(hb1, wg.y, ag1);
                ao0 = ffma2(hb0, wo.y, ao0); ao1 = ffma2(hb1, wo.y, ao1);
            }
            // All 8 horizontal sums first, then activation chains grouped so
            // their MUFU latencies overlap (and across 4 unrolled jj's).
            float2 p;
            p = unpack2(ai0); const float gi0 = p.x + p.y;
            p = unpack2(af0); const float gf0 = p.x + p.y;
            p = unpack2(ag0); const float gg0 = p.x + p.y;
            p = unpack2(ao0); const float go0 = p.x + p.y;
            p = unpack2(ai1); const float gi1 = p.x + p.y;
            p = unpack2(af1); const float gf1 = p.x + p.y;
            p = unpack2(ag1); const float gg1 = p.x + p.y;
            p = unpack2(ao1); const float go1 = p.x + p.y;

            const float si0 = sigf(gi0), si1 = sigf(gi1);
            const float sf0 = sigf(gf0), sf1 = sigf(gf1);
            const float tg0 = tanh_fast(gg0), tg1 = tanh_fast(gg1);
            const float so0 = sigf(go0), so1 = sigf(go1);

            const float cn0 = fmaf(sf0, c0[jj], si0 * tg0);
            const float cn1 = fmaf(sf1, c1[jj], si1 * tg1);
            c0[jj] = cn0;
            c1[jj] = cn1;
            const float hv0 = so0 * tanh_fast(cn0);
            const float hv1 = so1 * tanh_fast(cn1);

            if ((jj & 1) == 0) {
                hp0 = hv0; hp1 = hv1;
            } else {
                const int kp = 10 * half + (jj >> 1);
                hs[kp][2 * pair]     = make_float2(hp0, hv0);
                hs[kp][2 * pair + 1] = make_float2(hp1, hv1);
            }
        }

        __syncwarp();
#pragma unroll
        for (int k = 0; k < NH / 2; k++) {
            float2 v0 = hs[k][2 * pair];
            float2 v1 = hs[k][2 * pair + 1];
            h0[k] = pack2(v0.x, v0.y);
            h1[k] = pack2(v1.x, v1.y);
        }
        __syncwarp();
    }

    // Final head: thread tid = 2p+half outputs seq base+tid using h(half)
    float hT[NH];
#pragma unroll
    for (int k = 0; k < NH / 2; k++) {
        float2 a = unpack2(half ? h1[k] : h0[k]);
        hT[2 * k]     = a.x;
        hT[2 * k + 1] = a.y;
    }
    const long long seq = base + tid;
    float best = -3.402823466e38f;
    int bidx = 0;
#pragma unroll
    for (int cls = 0; cls < NC; cls++) {
        float acc = bfc_s[cls];
#pragma unroll
        for (int k = 0; k < NH; k++) acc = fmaf(hT[k], Wfc_s[cls * NH + k], acc);
        if (write_logits) out[seq * NC + cls] = acc;
        if (acc > best) { best = acc; bidx = cls; }
    }
    if (write_argmax) out[arg_off + seq] = (float)bidx;
}

extern "C" void kernel_launch(void* const* d_in, const int* in_sizes, int n_in,
                              void* d_out, int out_size)
{
    const float* x    = (const float*)d_in[0];
    const float* W_ih = (const float*)d_in[1];
    const float* W_hh = (const float*)d_in[2];
    const float* b_ih = (const float*)d_in[3];
    const float* b_hh = (const float*)d_in[4];
    const float* W_fc = (const float*)d_in[5];
    const float* b_fc = (const float*)d_in[6];
    float* out = (float*)d_out;

    // NOTE: no PreferredSharedMemoryCarveout — costs L1D, no occupancy gain.

    const long long B = (long long)in_sizes[0] / NT;

    int write_logits = 1, write_argmax = 0;
    long long arg_off = 0;
    if ((long long)out_size >= B * (NC + 1)) {
        write_logits = 1; write_argmax = 1; arg_off = B * NC;
    } else if ((long long)out_size >= B * NC) {
        write_logits = 1; write_argmax = 0;
    } else {
        write_logits = 0; write_argmax = 1; arg_off = 0;
    }

    const int grid = (int)((B + TPB - 1) / TPB);   // 128 seqs per block
    lstm_head_kernel<<<grid, TPB>>>(x, W_ih, W_hh, b_ih, b_hh, W_fc, b_fc,
                                    out, write_logits, write_argmax, arg_off);
}